// round 4
// baseline (speedup 1.0000x reference)
#include <cuda_runtime.h>
#include <math.h>
#include <cstdint>

#define MAXN   50000
#define MAXE   10000
#define MAXNNZ 600000

// ---------------- scratch (static __device__, no allocations) ----------------
__device__ float g_xh[MAXN * 256];    // x @ W1
__device__ float g_he[MAXE * 256];    // hyperedge_attr @ W1
__device__ float g_ax[MAXN * 4];
__device__ float g_ae[MAXE * 4];
__device__ float g_alpha[MAXNNZ * 4];
__device__ float g_eh[MAXE * 256];
__device__ float g_h[MAXN * 256];
__device__ float g_xh2[MAXN * 64];
__device__ float g_eh2[MAXE * 64];
__device__ int g_cntN[MAXN], g_cntE[MAXE];
__device__ int g_curN[MAXN], g_curE[MAXE];
__device__ int g_offN[MAXN], g_offE[MAXE];
__device__ int g_csrN[MAXNNZ], g_csrE[MAXNNZ];
__device__ int g_totN, g_totE;

// ---------------- tf32 helpers ----------------
__device__ __forceinline__ void split_tf32(float x, uint32_t& hi, uint32_t& lo) {
    uint32_t h;
    asm("cvt.rna.tf32.f32 %0, %1;" : "=r"(h) : "f"(x));
    float r = x - __uint_as_float(h);   // tf32 bit pattern is a valid fp32
    uint32_t l;
    asm("cvt.rna.tf32.f32 %0, %1;" : "=r"(l) : "f"(r));
    hi = h; lo = l;
}

__device__ __forceinline__ void mma_tf32(float* c, const uint32_t* a, const uint32_t* b) {
    asm volatile(
        "mma.sync.aligned.m16n8k8.row.col.f32.tf32.tf32.f32 "
        "{%0,%1,%2,%3}, {%4,%5,%6,%7}, {%8,%9}, {%0,%1,%2,%3};"
        : "+f"(c[0]), "+f"(c[1]), "+f"(c[2]), "+f"(c[3])
        : "r"(a[0]), "r"(a[1]), "r"(a[2]), "r"(a[3]), "r"(b[0]), "r"(b[1]));
}

// ---------------- 3xTF32 tensor-core GEMM: C[M,Nglob] = A[M,K] @ B[K,Nglob] ----------------
// BM=128, BK=32, 256 threads = 8 warps arranged WM x WN.
template <int K, int BN, int WM, int WN>
__global__ __launch_bounds__(256) void mmagemm_kernel(const float* __restrict__ A,
                                                      const float* __restrict__ B,
                                                      float* __restrict__ C, int M, int Nglob) {
    constexpr int BM = 128, BK = 32;
    constexpr int WTM = BM / WM;   // warp tile rows
    constexpr int WTN = BN / WN;   // warp tile cols
    constexpr int MT = WTM / 16;   // m16 tiles per warp
    constexpr int NT = WTN / 8;    // n8 tiles per warp
    constexpr int LDS = BK + 4;    // padded smem row (floats)

    extern __shared__ uint32_t sm[];
    uint32_t* AsH = sm;                    // [BM][LDS]
    uint32_t* AsL = AsH + BM * LDS;
    uint32_t* BsH = AsL + BM * LDS;        // [BN][LDS]
    uint32_t* BsL = BsH + BN * LDS;

    int tid = threadIdx.x;
    int wid = tid >> 5, lane = tid & 31;
    int warpM = wid / WN, warpN = wid % WN;
    int rowBase = blockIdx.x * BM;
    int colBase = blockIdx.y * BN;
    int gid = lane >> 2, tig = lane & 3;

    float acc[MT][NT][4] = {};

    for (int kt = 0; kt < K; kt += BK) {
        // ---- A tile [BM, BK], hi/lo split ----
        #pragma unroll
        for (int l = tid; l < BM * (BK / 4); l += 256) {
            int r = l / (BK / 4);
            int c = (l % (BK / 4)) * 4;
            int gr = rowBase + r;
            float4 v = make_float4(0.f, 0.f, 0.f, 0.f);
            if (gr < M) v = *(const float4*)&A[(size_t)gr * K + kt + c];
            uint32_t h0, l0, h1, l1, h2, l2, h3, l3;
            split_tf32(v.x, h0, l0); split_tf32(v.y, h1, l1);
            split_tf32(v.z, h2, l2); split_tf32(v.w, h3, l3);
            uint32_t* pH = &AsH[r * LDS + c];
            uint32_t* pL = &AsL[r * LDS + c];
            pH[0] = h0; pH[1] = h1; pH[2] = h2; pH[3] = h3;
            pL[0] = l0; pL[1] = l1; pL[2] = l2; pL[3] = l3;
        }
        // ---- B tile transposed: Bs[n][k] = B[kt+k][colBase+n] ----
        #pragma unroll
        for (int l = tid; l < BK * (BN / 4); l += 256) {
            int k = l / (BN / 4);
            int n = (l % (BN / 4)) * 4;
            float4 v = *(const float4*)&B[(size_t)(kt + k) * Nglob + colBase + n];
            uint32_t h, lo;
            split_tf32(v.x, h, lo); BsH[(n + 0) * LDS + k] = h; BsL[(n + 0) * LDS + k] = lo;
            split_tf32(v.y, h, lo); BsH[(n + 1) * LDS + k] = h; BsL[(n + 1) * LDS + k] = lo;
            split_tf32(v.z, h, lo); BsH[(n + 2) * LDS + k] = h; BsL[(n + 2) * LDS + k] = lo;
            split_tf32(v.w, h, lo); BsH[(n + 3) * LDS + k] = h; BsL[(n + 3) * LDS + k] = lo;
        }
        __syncthreads();

        #pragma unroll
        for (int ks = 0; ks < BK / 8; ks++) {
            uint32_t aH[MT][4], aL[MT][4], bH[NT][2], bL[NT][2];
            int c0 = ks * 8 + tig;
            #pragma unroll
            for (int mt = 0; mt < MT; mt++) {
                int r0 = warpM * WTM + mt * 16 + gid;
                const uint32_t* pH = &AsH[r0 * LDS + c0];
                const uint32_t* pL = &AsL[r0 * LDS + c0];
                aH[mt][0] = pH[0]; aH[mt][1] = pH[8 * LDS];
                aH[mt][2] = pH[4]; aH[mt][3] = pH[8 * LDS + 4];
                aL[mt][0] = pL[0]; aL[mt][1] = pL[8 * LDS];
                aL[mt][2] = pL[4]; aL[mt][3] = pL[8 * LDS + 4];
            }
            #pragma unroll
            for (int nt = 0; nt < NT; nt++) {
                int n0 = warpN * WTN + nt * 8 + gid;
                bH[nt][0] = BsH[n0 * LDS + c0]; bH[nt][1] = BsH[n0 * LDS + c0 + 4];
                bL[nt][0] = BsL[n0 * LDS + c0]; bL[nt][1] = BsL[n0 * LDS + c0 + 4];
            }
            #pragma unroll
            for (int mt = 0; mt < MT; mt++)
                #pragma unroll
                for (int nt = 0; nt < NT; nt++) {
                    mma_tf32(acc[mt][nt], aH[mt], bH[nt]);
                    mma_tf32(acc[mt][nt], aH[mt], bL[nt]);
                    mma_tf32(acc[mt][nt], aL[mt], bH[nt]);
                }
        }
        __syncthreads();
    }

    // ---- epilogue ----
    #pragma unroll
    for (int mt = 0; mt < MT; mt++) {
        int r0 = rowBase + warpM * WTM + mt * 16 + gid;
        #pragma unroll
        for (int nt = 0; nt < NT; nt++) {
            int c = colBase + warpN * WTN + nt * 8 + tig * 2;
            if (r0 < M)
                *(float2*)&C[(size_t)r0 * Nglob + c] = make_float2(acc[mt][nt][0], acc[mt][nt][1]);
            if (r0 + 8 < M)
                *(float2*)&C[(size_t)(r0 + 8) * Nglob + c] = make_float2(acc[mt][nt][2], acc[mt][nt][3]);
        }
    }
}

// ---------------- CSR construction ----------------
__global__ void zero_counts_kernel(int N, int E) {
    int i = blockIdx.x * blockDim.x + threadIdx.x;
    int s = gridDim.x * blockDim.x;
    if (i == 0) { g_totN = 0; g_totE = 0; }
    for (int j = i; j < N; j += s) { g_cntN[j] = 0; g_curN[j] = 0; }
    for (int j = i; j < E; j += s) { g_cntE[j] = 0; g_curE[j] = 0; }
}

__global__ void count_kernel(const int* __restrict__ node, const int* __restrict__ hedge, int nnz) {
    int i = blockIdx.x * blockDim.x + threadIdx.x;
    int s = gridDim.x * blockDim.x;
    for (int j = i; j < nnz; j += s) {
        atomicAdd(&g_cntN[node[j]], 1);
        atomicAdd(&g_cntE[hedge[j]], 1);
    }
}

__device__ __forceinline__ void alloc_ranges(const int* __restrict__ cnt, int* __restrict__ off,
                                             int* total, int n, int gwarp, int nwarps, int lane) {
    for (int j0 = gwarp * 32; j0 < n; j0 += nwarps * 32) {
        int j = j0 + lane;
        int c = (j < n) ? cnt[j] : 0;
        int x = c;
        #pragma unroll
        for (int o = 1; o < 32; o <<= 1) {
            int y = __shfl_up_sync(0xffffffffu, x, o);
            if (lane >= o) x += y;
        }
        int wtot = __shfl_sync(0xffffffffu, x, 31);
        int base = 0;
        if (lane == 0) base = atomicAdd(total, wtot);
        base = __shfl_sync(0xffffffffu, base, 0);
        if (j < n) off[j] = base + x - c;
    }
}

__global__ void alloc_kernel(int N, int E) {
    int t = blockIdx.x * blockDim.x + threadIdx.x;
    int gwarp = t >> 5, lane = t & 31;
    int nwarps = (gridDim.x * blockDim.x) >> 5;
    alloc_ranges(g_cntN, g_offN, &g_totN, N, gwarp, nwarps, lane);
    alloc_ranges(g_cntE, g_offE, &g_totE, E, gwarp, nwarps, lane);
}

__global__ void scatter_kernel(const int* __restrict__ node, const int* __restrict__ hedge, int nnz) {
    int i = blockIdx.x * blockDim.x + threadIdx.x;
    int s = gridDim.x * blockDim.x;
    for (int j = i; j < nnz; j += s) {
        int pn = g_offN[node[j]] + atomicAdd(&g_curN[node[j]], 1);
        g_csrN[pn] = j;
        int pe = g_offE[hedge[j]] + atomicAdd(&g_curE[hedge[j]], 1);
        g_csrE[pe] = j;
    }
}

// ---------------- attention row-dots ----------------
__global__ void rowdot_kernel(const float* __restrict__ src, const float* __restrict__ att,
                              float* __restrict__ out, int attOff) {
    int n = blockIdx.x;
    int t = threadIdx.x;
    int h = t >> 6, f = t & 63;
    float v = src[n * 256 + t] * att[h * 128 + attOff + f];
    #pragma unroll
    for (int o = 16; o; o >>= 1) v += __shfl_xor_sync(0xffffffffu, v, o);
    __shared__ float w[8];
    if ((t & 31) == 0) w[t >> 5] = v;
    __syncthreads();
    if (t < 4) out[n * 4 + t] = w[2 * t] + w[2 * t + 1];
}

// ---------------- conv1 edge stage: segment softmax + propagate 1 ----------------
#define ECAP 1024
__global__ __launch_bounds__(256) void edge1_kernel(const int* __restrict__ nodeIdx) {
    int e = blockIdx.x;
    int tid = threadIdx.x;
    int lane = tid & 31, warp = tid >> 5;
    int beg = g_offE[e];
    int k = g_cntE[e];
    float aeh[4];
    #pragma unroll
    for (int h = 0; h < 4; h++) aeh[h] = g_ae[e * 4 + h];

    __shared__ int snode[ECAP];
    __shared__ int sidx[ECAP];
    __shared__ float slog[ECAP * 4];
    __shared__ float4 racc[256];
    __shared__ float wr[8][4];
    __shared__ float smax[4], sinv[4];

    int g = tid >> 6, f4 = tid & 63, hh = f4 >> 4;
    float Binv = k > 0 ? 1.f / (float)k : 0.f;
    float4 acc = make_float4(0.f, 0.f, 0.f, 0.f);
    const float4* xh4 = (const float4*)g_xh;

    if (k <= ECAP) {
        float lmax[4] = {-1e30f, -1e30f, -1e30f, -1e30f};
        for (int j = tid; j < k; j += 256) {
            int i = g_csrE[beg + j];
            int n = nodeIdx[i];
            sidx[j] = i;
            snode[j] = n;
            #pragma unroll
            for (int h = 0; h < 4; h++) {
                float z = g_ax[n * 4 + h] + aeh[h];
                z = z > 0.f ? z : 0.2f * z;
                slog[j * 4 + h] = z;
                lmax[h] = fmaxf(lmax[h], z);
            }
        }
        #pragma unroll
        for (int o = 16; o; o >>= 1)
            #pragma unroll
            for (int h = 0; h < 4; h++)
                lmax[h] = fmaxf(lmax[h], __shfl_xor_sync(0xffffffffu, lmax[h], o));
        if (lane == 0)
            #pragma unroll
            for (int h = 0; h < 4; h++) wr[warp][h] = lmax[h];
        __syncthreads();
        if (tid < 4) {
            float r = wr[0][tid];
            #pragma unroll
            for (int w2 = 1; w2 < 8; w2++) r = fmaxf(r, wr[w2][tid]);
            smax[tid] = r;
        }
        __syncthreads();

        float lsum[4] = {0.f, 0.f, 0.f, 0.f};
        for (int j = tid; j < k; j += 256) {
            #pragma unroll
            for (int h = 0; h < 4; h++) {
                float ex = __expf(slog[j * 4 + h] - smax[h]);
                slog[j * 4 + h] = ex;
                lsum[h] += ex;
            }
        }
        #pragma unroll
        for (int o = 16; o; o >>= 1)
            #pragma unroll
            for (int h = 0; h < 4; h++) lsum[h] += __shfl_xor_sync(0xffffffffu, lsum[h], o);
        if (lane == 0)
            #pragma unroll
            for (int h = 0; h < 4; h++) wr[warp][h] = lsum[h];
        __syncthreads();
        if (tid < 4) {
            float r = wr[0][tid];
            #pragma unroll
            for (int w2 = 1; w2 < 8; w2++) r += wr[w2][tid];
            sinv[tid] = 1.f / (r + 1e-16f);
        }
        __syncthreads();

        for (int j = tid; j < k; j += 256) {
            float4 a;
            a.x = slog[j * 4 + 0] * sinv[0];
            a.y = slog[j * 4 + 1] * sinv[1];
            a.z = slog[j * 4 + 2] * sinv[2];
            a.w = slog[j * 4 + 3] * sinv[3];
            slog[j * 4 + 0] = a.x; slog[j * 4 + 1] = a.y;
            slog[j * 4 + 2] = a.z; slog[j * 4 + 3] = a.w;
            ((float4*)g_alpha)[sidx[j]] = a;
        }
        __syncthreads();

        for (int j = g; j < k; j += 4) {
            float a = slog[j * 4 + hh];
            float4 xv = xh4[snode[j] * 64 + f4];
            acc.x += a * xv.x; acc.y += a * xv.y; acc.z += a * xv.z; acc.w += a * xv.w;
        }
    } else {
        float lmax[4] = {-1e30f, -1e30f, -1e30f, -1e30f};
        for (int j = tid; j < k; j += 256) {
            int i = g_csrE[beg + j];
            int n = nodeIdx[i];
            #pragma unroll
            for (int h = 0; h < 4; h++) {
                float z = g_ax[n * 4 + h] + aeh[h];
                z = z > 0.f ? z : 0.2f * z;
                g_alpha[i * 4 + h] = z;
                lmax[h] = fmaxf(lmax[h], z);
            }
        }
        #pragma unroll
        for (int o = 16; o; o >>= 1)
            #pragma unroll
            for (int h = 0; h < 4; h++)
                lmax[h] = fmaxf(lmax[h], __shfl_xor_sync(0xffffffffu, lmax[h], o));
        if (lane == 0)
            #pragma unroll
            for (int h = 0; h < 4; h++) wr[warp][h] = lmax[h];
        __syncthreads();
        if (tid < 4) {
            float r = wr[0][tid];
            #pragma unroll
            for (int w2 = 1; w2 < 8; w2++) r = fmaxf(r, wr[w2][tid]);
            smax[tid] = r;
        }
        __syncthreads();
        float lsum[4] = {0.f, 0.f, 0.f, 0.f};
        for (int j = tid; j < k; j += 256) {
            int i = g_csrE[beg + j];
            #pragma unroll
            for (int h = 0; h < 4; h++) {
                float ex = __expf(g_alpha[i * 4 + h] - smax[h]);
                g_alpha[i * 4 + h] = ex;
                lsum[h] += ex;
            }
        }
        #pragma unroll
        for (int o = 16; o; o >>= 1)
            #pragma unroll
            for (int h = 0; h < 4; h++) lsum[h] += __shfl_xor_sync(0xffffffffu, lsum[h], o);
        if (lane == 0)
            #pragma unroll
            for (int h = 0; h < 4; h++) wr[warp][h] = lsum[h];
        __syncthreads();
        if (tid < 4) {
            float r = wr[0][tid];
            #pragma unroll
            for (int w2 = 1; w2 < 8; w2++) r += wr[w2][tid];
            sinv[tid] = 1.f / (r + 1e-16f);
        }
        __syncthreads();
        for (int j = tid; j < k; j += 256) {
            int i = g_csrE[beg + j];
            #pragma unroll
            for (int h = 0; h < 4; h++) g_alpha[i * 4 + h] *= sinv[h];
        }
        __syncthreads();
        for (int base = 0; base < k; base += ECAP) {
            int c = min(ECAP, k - base);
            __syncthreads();
            for (int j = tid; j < c; j += 256) {
                int i = g_csrE[beg + base + j];
                snode[j] = nodeIdx[i];
                ((float4*)slog)[j] = ((const float4*)g_alpha)[i];
            }
            __syncthreads();
            for (int j = g; j < c; j += 4) {
                float a = slog[j * 4 + hh];
                float4 xv = xh4[snode[j] * 64 + f4];
                acc.x += a * xv.x; acc.y += a * xv.y; acc.z += a * xv.z; acc.w += a * xv.w;
            }
        }
    }

    racc[tid] = acc;
    __syncthreads();
    if (tid < 64) {
        float4 a = racc[tid], b = racc[tid + 64], c2 = racc[tid + 128], d2 = racc[tid + 192];
        float4 r;
        r.x = (a.x + b.x + c2.x + d2.x) * Binv;
        r.y = (a.y + b.y + c2.y + d2.y) * Binv;
        r.z = (a.z + b.z + c2.z + d2.z) * Binv;
        r.w = (a.w + b.w + c2.w + d2.w) * Binv;
        ((float4*)g_eh)[e * 64 + tid] = r;
    }
}

__device__ __forceinline__ float eluf(float x) { return x > 0.f ? x : expm1f(x); }

// ---------------- conv1 node stage ----------------
__global__ __launch_bounds__(256) void node1_kernel(const int* __restrict__ hedgeIdx,
                                                    const float* __restrict__ b1) {
    int n = blockIdx.x;
    int tid = threadIdx.x;
    int beg = g_offN[n];
    int d = g_cntN[n];
    int end = beg + d;
    float Dinv = d > 0 ? 1.f / (float)d : 0.f;
    int g = tid >> 6, f4 = tid & 63, h = f4 >> 4;
    float4 acc = make_float4(0.f, 0.f, 0.f, 0.f);
    const float4* eh4 = (const float4*)g_eh;
    for (int j = beg + g; j < end; j += 4) {
        int i = g_csrN[j];
        int e = hedgeIdx[i];
        float a = g_alpha[i * 4 + h];
        float4 ev = eh4[e * 64 + f4];
        acc.x += a * ev.x; acc.y += a * ev.y; acc.z += a * ev.z; acc.w += a * ev.w;
    }
    __shared__ float4 racc[256];
    racc[tid] = acc;
    __syncthreads();
    if (tid < 64) {
        float4 a = racc[tid], b = racc[tid + 64], c2 = racc[tid + 128], d2 = racc[tid + 192];
        float4 bv = ((const float4*)b1)[tid];
        float4 r;
        r.x = eluf((a.x + b.x + c2.x + d2.x) * Dinv + bv.x);
        r.y = eluf((a.y + b.y + c2.y + d2.y) * Dinv + bv.y);
        r.z = eluf((a.z + b.z + c2.z + d2.z) * Dinv + bv.z);
        r.w = eluf((a.w + b.w + c2.w + d2.w) * Dinv + bv.w);
        ((float4*)g_h)[n * 64 + tid] = r;
    }
}

// ---------------- conv2 ----------------
__global__ __launch_bounds__(256) void edge2_kernel(const int* __restrict__ nodeIdx) {
    int e = blockIdx.x;
    int tid = threadIdx.x;
    int beg = g_offE[e];
    int k = g_cntE[e];
    int end = beg + k;
    float Binv = k > 0 ? 1.f / (float)k : 0.f;
    int g = tid >> 6, f = tid & 63;
    float acc = 0.f;
    for (int j = beg + g; j < end; j += 4) {
        int i = g_csrE[j];
        int n = nodeIdx[i];
        acc += g_xh2[n * 64 + f];
    }
    __shared__ float racc[256];
    racc[tid] = acc;
    __syncthreads();
    if (tid < 64)
        g_eh2[e * 64 + tid] = (racc[tid] + racc[tid + 64] + racc[tid + 128] + racc[tid + 192]) * Binv;
}

__global__ __launch_bounds__(256) void node2_kernel(const int* __restrict__ hedgeIdx,
                                                    const float* __restrict__ b2,
                                                    float* __restrict__ out) {
    int n = blockIdx.x;
    int tid = threadIdx.x;
    int beg = g_offN[n];
    int d = g_cntN[n];
    int end = beg + d;
    float Dinv = d > 0 ? 1.f / (float)d : 0.f;
    int g = tid >> 6, f = tid & 63;
    float acc = 0.f;
    for (int j = beg + g; j < end; j += 4) {
        int i = g_csrN[j];
        int e = hedgeIdx[i];
        acc += g_eh2[e * 64 + f];
    }
    __shared__ float racc[256];
    racc[tid] = acc;
    __syncthreads();
    if (tid < 64)
        out[n * 64 + tid] =
            (racc[tid] + racc[tid + 64] + racc[tid + 128] + racc[tid + 192]) * Dinv + b2[tid];
}

// ---------------- launch ----------------
extern "C" void kernel_launch(void* const* d_in, const int* in_sizes, int n_in,
                              void* d_out, int out_size) {
    const float* x    = (const float*)d_in[0];
    const int*   ei   = (const int*)d_in[1];
    const float* hat  = (const float*)d_in[2];
    const float* W1   = (const float*)d_in[3];
    const float* att1 = (const float*)d_in[4];
    const float* b1   = (const float*)d_in[5];
    const float* W2   = (const float*)d_in[6];
    const float* b2   = (const float*)d_in[7];
    float* out = (float*)d_out;

    int N   = in_sizes[0] / 128;
    int NNZ = in_sizes[1] / 2;
    int E   = in_sizes[2] / 128;
    const int* node  = ei;
    const int* hedge = ei + NNZ;

    float *p_xh, *p_he, *p_h, *p_xh2, *p_ax, *p_ae;
    cudaGetSymbolAddress((void**)&p_xh, g_xh);
    cudaGetSymbolAddress((void**)&p_he, g_he);
    cudaGetSymbolAddress((void**)&p_h, g_h);
    cudaGetSymbolAddress((void**)&p_xh2, g_xh2);
    cudaGetSymbolAddress((void**)&p_ax, g_ax);
    cudaGetSymbolAddress((void**)&p_ae, g_ae);

    // dynamic smem: (BM + BN) * 36 floats * 2 (hi/lo) * 4 bytes
    const int SMEM_G1 = (128 + 128) * 36 * 2 * 4;  // 73728
    const int SMEM_G3 = (128 + 64) * 36 * 2 * 4;   // 55296
    cudaFuncSetAttribute(mmagemm_kernel<128, 128, 2, 4>,
                         cudaFuncAttributeMaxDynamicSharedMemorySize, SMEM_G1);
    cudaFuncSetAttribute(mmagemm_kernel<256, 64, 4, 2>,
                         cudaFuncAttributeMaxDynamicSharedMemorySize, SMEM_G3);

    // CSR build (unordered contiguous ranges)
    zero_counts_kernel<<<128, 256>>>(N, E);
    count_kernel<<<480, 256>>>(node, hedge, NNZ);
    alloc_kernel<<<64, 256>>>(N, E);
    scatter_kernel<<<480, 256>>>(node, hedge, NNZ);

    // conv1 GEMMs on tensor cores (3xTF32)
    mmagemm_kernel<128, 128, 2, 4><<<dim3((N + 127) / 128, 2), 256, SMEM_G1>>>(x, W1, p_xh, N, 256);
    mmagemm_kernel<128, 128, 2, 4><<<dim3((E + 127) / 128, 2), 256, SMEM_G1>>>(hat, W1, p_he, E, 256);

    // attention dots
    rowdot_kernel<<<N, 256>>>(p_xh, att1, p_ax, 0);
    rowdot_kernel<<<E, 256>>>(p_he, att1, p_ae, 64);

    // conv1: softmax + propagates + elu
    edge1_kernel<<<E, 256>>>(node);
    node1_kernel<<<N, 256>>>(hedge, b1);

    // conv2
    mmagemm_kernel<256, 64, 4, 2><<<dim3((N + 127) / 128, 1), 256, SMEM_G3>>>(p_h, W2, p_xh2, N, 64);
    edge2_kernel<<<E, 256>>>(node);
    node2_kernel<<<N, 256>>>(hedge, b2, out);
}

// round 5
// speedup vs baseline: 1.0871x; 1.0871x over previous
#include <cuda_runtime.h>
#include <math.h>
#include <cstdint>

#define MAXN   50000
#define MAXE   10000
#define MAXNNZ 600000

// ---------------- scratch (static __device__, no allocations) ----------------
__device__ float g_xh[MAXN * 256];    // x @ W1
__device__ float g_ax[MAXN * 4];      // x @ A1 (attention logit, node part)
__device__ float g_ae[MAXE * 4];      // hat @ A2 (attention logit, edge part)
__device__ float g_A1[128 * 4];       // W1 folded with att (first half)
__device__ float g_A2[128 * 4];       // W1 folded with att (second half)
__device__ float g_alpha[MAXNNZ * 4];
__device__ float g_eh[MAXE * 256];
__device__ float g_h[MAXN * 256];
__device__ float g_xh2[MAXN * 64];
__device__ float g_eh2[MAXE * 64];
__device__ int g_cntN[MAXN], g_cntE[MAXE];
__device__ int g_curN[MAXN], g_curE[MAXE];
__device__ int g_offN[MAXN], g_offE[MAXE];
__device__ int g_csrN[MAXNNZ], g_csrE[MAXNNZ];
__device__ int g_totN, g_totE;

// ---------------- CSR construction ----------------
__global__ void zero_counts_kernel(int N, int E) {
    int i = blockIdx.x * blockDim.x + threadIdx.x;
    int s = gridDim.x * blockDim.x;
    if (i == 0) { g_totN = 0; g_totE = 0; }
    for (int j = i; j < N; j += s) { g_cntN[j] = 0; g_curN[j] = 0; }
    for (int j = i; j < E; j += s) { g_cntE[j] = 0; g_curE[j] = 0; }
}

__global__ void count_kernel(const int* __restrict__ node, const int* __restrict__ hedge, int nnz) {
    int i = blockIdx.x * blockDim.x + threadIdx.x;
    int s = gridDim.x * blockDim.x;
    for (int j = i; j < nnz; j += s) {
        atomicAdd(&g_cntN[node[j]], 1);
        atomicAdd(&g_cntE[hedge[j]], 1);
    }
}

__device__ __forceinline__ void alloc_ranges(const int* __restrict__ cnt, int* __restrict__ off,
                                             int* total, int n, int gwarp, int nwarps, int lane) {
    for (int j0 = gwarp * 32; j0 < n; j0 += nwarps * 32) {
        int j = j0 + lane;
        int c = (j < n) ? cnt[j] : 0;
        int x = c;
        #pragma unroll
        for (int o = 1; o < 32; o <<= 1) {
            int y = __shfl_up_sync(0xffffffffu, x, o);
            if (lane >= o) x += y;
        }
        int wtot = __shfl_sync(0xffffffffu, x, 31);
        int base = 0;
        if (lane == 0) base = atomicAdd(total, wtot);
        base = __shfl_sync(0xffffffffu, base, 0);
        if (j < n) off[j] = base + x - c;
    }
}

__global__ void alloc_kernel(int N, int E) {
    int t = blockIdx.x * blockDim.x + threadIdx.x;
    int gwarp = t >> 5, lane = t & 31;
    int nwarps = (gridDim.x * blockDim.x) >> 5;
    alloc_ranges(g_cntN, g_offN, &g_totN, N, gwarp, nwarps, lane);
    alloc_ranges(g_cntE, g_offE, &g_totE, E, gwarp, nwarps, lane);
}

__global__ void scatter_kernel(const int* __restrict__ node, const int* __restrict__ hedge, int nnz) {
    int i = blockIdx.x * blockDim.x + threadIdx.x;
    int s = gridDim.x * blockDim.x;
    for (int j = i; j < nnz; j += s) {
        int pn = g_offN[node[j]] + atomicAdd(&g_curN[node[j]], 1);
        g_csrN[pn] = j;
        int pe = g_offE[hedge[j]] + atomicAdd(&g_curE[hedge[j]], 1);
        g_csrE[pe] = j;
    }
}

// ---------------- tiled fp32 GEMM: C[M,N] = A[M,K] @ B[K,N] ----------------
template <int BM, int BN, int BK, int TM, int TN>
__global__ __launch_bounds__(256) void sgemm_kernel(const float* __restrict__ A,
                                                    const float* __restrict__ B,
                                                    float* __restrict__ C, int M, int N, int K) {
    constexpr int THREADS = (BM / TM) * (BN / TN);
    __shared__ float As[BK][BM];
    __shared__ float Bs[BK][BN];
    int tid = threadIdx.x;
    int tx = tid % (BN / TN);
    int ty = tid / (BN / TN);
    int rowBase = blockIdx.x * BM;
    int colBase = blockIdx.y * BN;
    float acc[TM][TN] = {};
    for (int kt = 0; kt < K; kt += BK) {
        #pragma unroll
        for (int l = tid; l < BM * BK / 4; l += THREADS) {
            int r = l / (BK / 4), c4 = l % (BK / 4);
            int gr = rowBase + r;
            float4 v = make_float4(0.f, 0.f, 0.f, 0.f);
            if (gr < M) v = *(const float4*)&A[(size_t)gr * K + kt + c4 * 4];
            As[c4 * 4 + 0][r] = v.x;
            As[c4 * 4 + 1][r] = v.y;
            As[c4 * 4 + 2][r] = v.z;
            As[c4 * 4 + 3][r] = v.w;
        }
        #pragma unroll
        for (int l = tid; l < BK * BN / 4; l += THREADS) {
            int r = l / (BN / 4), c4 = l % (BN / 4);
            *(float4*)&Bs[r][c4 * 4] = *(const float4*)&B[(size_t)(kt + r) * N + colBase + c4 * 4];
        }
        __syncthreads();
        #pragma unroll
        for (int k = 0; k < BK; k++) {
            float ar[TM], br[TN];
            #pragma unroll
            for (int i = 0; i < TM; i++) ar[i] = As[k][ty * TM + i];
            #pragma unroll
            for (int j = 0; j < TN; j++) br[j] = Bs[k][tx * TN + j];
            #pragma unroll
            for (int i = 0; i < TM; i++)
                #pragma unroll
                for (int j = 0; j < TN; j++) acc[i][j] += ar[i] * br[j];
        }
        __syncthreads();
    }
    #pragma unroll
    for (int i = 0; i < TM; i++) {
        int gr = rowBase + ty * TM + i;
        if (gr < M) {
            #pragma unroll
            for (int j4 = 0; j4 < TN / 4; j4++) {
                float4 v = make_float4(acc[i][j4 * 4 + 0], acc[i][j4 * 4 + 1],
                                       acc[i][j4 * 4 + 2], acc[i][j4 * 4 + 3]);
                *(float4*)&C[(size_t)gr * N + colBase + tx * TN + j4 * 4] = v;
            }
        }
    }
}

// ---------------- fold att into W1: A1[k,h] = sum_f W1[k, h*64+f] * att[h*128+f] ----------------
__global__ void attmat_kernel(const float* __restrict__ W1, const float* __restrict__ att) {
    int t = threadIdx.x;           // 512 threads
    int k = t >> 2, h = t & 3;
    const float* wrow = &W1[k * 256 + h * 64];
    const float* a1 = &att[h * 128];
    const float* a2 = &att[h * 128 + 64];
    float s1 = 0.f, s2 = 0.f;
    #pragma unroll
    for (int f = 0; f < 64; f++) {
        float w = wrow[f];
        s1 += w * a1[f];
        s2 += w * a2[f];
    }
    g_A1[k * 4 + h] = s1;
    g_A2[k * 4 + h] = s2;
}

// ---------------- attention logits: ax = x @ A1 (rows < N), ae = hat @ A2 ----------------
__global__ __launch_bounds__(256) void axae_kernel(const float* __restrict__ x,
                                                   const float* __restrict__ hat, int N, int E) {
    __shared__ float sA1[128 * 4], sA2[128 * 4];
    int tid = threadIdx.x;
    for (int i = tid; i < 512; i += 256) { sA1[i] = g_A1[i]; sA2[i] = g_A2[i]; }
    __syncthreads();
    int r = blockIdx.x * 256 + tid;
    if (r >= N + E) return;
    bool isNode = r < N;
    const float4* row = (const float4*)(isNode ? &x[(size_t)r * 128] : &hat[(size_t)(r - N) * 128]);
    const float* Am = isNode ? sA1 : sA2;
    float acc0 = 0.f, acc1 = 0.f, acc2 = 0.f, acc3 = 0.f;
    #pragma unroll
    for (int k4 = 0; k4 < 32; k4++) {
        float4 v = row[k4];
        const float* a = &Am[k4 * 16];
        acc0 += v.x * a[0];  acc1 += v.x * a[1];  acc2 += v.x * a[2];  acc3 += v.x * a[3];
        acc0 += v.y * a[4];  acc1 += v.y * a[5];  acc2 += v.y * a[6];  acc3 += v.y * a[7];
        acc0 += v.z * a[8];  acc1 += v.z * a[9];  acc2 += v.z * a[10]; acc3 += v.z * a[11];
        acc0 += v.w * a[12]; acc1 += v.w * a[13]; acc2 += v.w * a[14]; acc3 += v.w * a[15];
    }
    float* dst = isNode ? &g_ax[r * 4] : &g_ae[(r - N) * 4];
    dst[0] = acc0; dst[1] = acc1; dst[2] = acc2; dst[3] = acc3;
}

// ---------------- conv1 edge stage: segment softmax + propagate 1 ----------------
#define ECAP 1024
__global__ __launch_bounds__(256) void edge1_kernel(const int* __restrict__ nodeIdx) {
    int e = blockIdx.x;
    int tid = threadIdx.x;
    int lane = tid & 31, warp = tid >> 5;
    int beg = g_offE[e];
    int k = g_cntE[e];
    float aeh[4];
    #pragma unroll
    for (int h = 0; h < 4; h++) aeh[h] = g_ae[e * 4 + h];

    __shared__ int snode[ECAP];
    __shared__ int sidx[ECAP];
    __shared__ float slog[ECAP * 4];
    __shared__ float4 racc[256];
    __shared__ float wr[8][4];
    __shared__ float smax[4], sinv[4];

    int g = tid >> 6, f4 = tid & 63, hh = f4 >> 4;
    float Binv = k > 0 ? 1.f / (float)k : 0.f;
    float4 acc = make_float4(0.f, 0.f, 0.f, 0.f);
    const float4* xh4 = (const float4*)g_xh;

    if (k <= ECAP) {
        float lmax[4] = {-1e30f, -1e30f, -1e30f, -1e30f};
        for (int j = tid; j < k; j += 256) {
            int i = g_csrE[beg + j];
            int n = nodeIdx[i];
            sidx[j] = i;
            snode[j] = n;
            #pragma unroll
            for (int h = 0; h < 4; h++) {
                float z = g_ax[n * 4 + h] + aeh[h];
                z = z > 0.f ? z : 0.2f * z;
                slog[j * 4 + h] = z;
                lmax[h] = fmaxf(lmax[h], z);
            }
        }
        #pragma unroll
        for (int o = 16; o; o >>= 1)
            #pragma unroll
            for (int h = 0; h < 4; h++)
                lmax[h] = fmaxf(lmax[h], __shfl_xor_sync(0xffffffffu, lmax[h], o));
        if (lane == 0)
            #pragma unroll
            for (int h = 0; h < 4; h++) wr[warp][h] = lmax[h];
        __syncthreads();
        if (tid < 4) {
            float r = wr[0][tid];
            #pragma unroll
            for (int w2 = 1; w2 < 8; w2++) r = fmaxf(r, wr[w2][tid]);
            smax[tid] = r;
        }
        __syncthreads();

        float lsum[4] = {0.f, 0.f, 0.f, 0.f};
        for (int j = tid; j < k; j += 256) {
            #pragma unroll
            for (int h = 0; h < 4; h++) {
                float ex = __expf(slog[j * 4 + h] - smax[h]);
                slog[j * 4 + h] = ex;
                lsum[h] += ex;
            }
        }
        #pragma unroll
        for (int o = 16; o; o >>= 1)
            #pragma unroll
            for (int h = 0; h < 4; h++) lsum[h] += __shfl_xor_sync(0xffffffffu, lsum[h], o);
        if (lane == 0)
            #pragma unroll
            for (int h = 0; h < 4; h++) wr[warp][h] = lsum[h];
        __syncthreads();
        if (tid < 4) {
            float r = wr[0][tid];
            #pragma unroll
            for (int w2 = 1; w2 < 8; w2++) r += wr[w2][tid];
            sinv[tid] = 1.f / (r + 1e-16f);
        }
        __syncthreads();

        for (int j = tid; j < k; j += 256) {
            float4 a;
            a.x = slog[j * 4 + 0] * sinv[0];
            a.y = slog[j * 4 + 1] * sinv[1];
            a.z = slog[j * 4 + 2] * sinv[2];
            a.w = slog[j * 4 + 3] * sinv[3];
            slog[j * 4 + 0] = a.x; slog[j * 4 + 1] = a.y;
            slog[j * 4 + 2] = a.z; slog[j * 4 + 3] = a.w;
            ((float4*)g_alpha)[sidx[j]] = a;
        }
        __syncthreads();

        for (int j = g; j < k; j += 4) {
            float a = slog[j * 4 + hh];
            float4 xv = xh4[snode[j] * 64 + f4];
            acc.x += a * xv.x; acc.y += a * xv.y; acc.z += a * xv.z; acc.w += a * xv.w;
        }
    } else {
        float lmax[4] = {-1e30f, -1e30f, -1e30f, -1e30f};
        for (int j = tid; j < k; j += 256) {
            int i = g_csrE[beg + j];
            int n = nodeIdx[i];
            #pragma unroll
            for (int h = 0; h < 4; h++) {
                float z = g_ax[n * 4 + h] + aeh[h];
                z = z > 0.f ? z : 0.2f * z;
                g_alpha[i * 4 + h] = z;
                lmax[h] = fmaxf(lmax[h], z);
            }
        }
        #pragma unroll
        for (int o = 16; o; o >>= 1)
            #pragma unroll
            for (int h = 0; h < 4; h++)
                lmax[h] = fmaxf(lmax[h], __shfl_xor_sync(0xffffffffu, lmax[h], o));
        if (lane == 0)
            #pragma unroll
            for (int h = 0; h < 4; h++) wr[warp][h] = lmax[h];
        __syncthreads();
        if (tid < 4) {
            float r = wr[0][tid];
            #pragma unroll
            for (int w2 = 1; w2 < 8; w2++) r = fmaxf(r, wr[w2][tid]);
            smax[tid] = r;
        }
        __syncthreads();
        float lsum[4] = {0.f, 0.f, 0.f, 0.f};
        for (int j = tid; j < k; j += 256) {
            int i = g_csrE[beg + j];
            #pragma unroll
            for (int h = 0; h < 4; h++) {
                float ex = __expf(g_alpha[i * 4 + h] - smax[h]);
                g_alpha[i * 4 + h] = ex;
                lsum[h] += ex;
            }
        }
        #pragma unroll
        for (int o = 16; o; o >>= 1)
            #pragma unroll
            for (int h = 0; h < 4; h++) lsum[h] += __shfl_xor_sync(0xffffffffu, lsum[h], o);
        if (lane == 0)
            #pragma unroll
            for (int h = 0; h < 4; h++) wr[warp][h] = lsum[h];
        __syncthreads();
        if (tid < 4) {
            float r = wr[0][tid];
            #pragma unroll
            for (int w2 = 1; w2 < 8; w2++) r += wr[w2][tid];
            sinv[tid] = 1.f / (r + 1e-16f);
        }
        __syncthreads();
        for (int j = tid; j < k; j += 256) {
            int i = g_csrE[beg + j];
            #pragma unroll
            for (int h = 0; h < 4; h++) g_alpha[i * 4 + h] *= sinv[h];
        }
        __syncthreads();
        for (int base = 0; base < k; base += ECAP) {
            int c = min(ECAP, k - base);
            __syncthreads();
            for (int j = tid; j < c; j += 256) {
                int i = g_csrE[beg + base + j];
                snode[j] = nodeIdx[i];
                ((float4*)slog)[j] = ((const float4*)g_alpha)[i];
            }
            __syncthreads();
            for (int j = g; j < c; j += 4) {
                float a = slog[j * 4 + hh];
                float4 xv = xh4[snode[j] * 64 + f4];
                acc.x += a * xv.x; acc.y += a * xv.y; acc.z += a * xv.z; acc.w += a * xv.w;
            }
        }
    }

    racc[tid] = acc;
    __syncthreads();
    if (tid < 64) {
        float4 a = racc[tid], b = racc[tid + 64], c2 = racc[tid + 128], d2 = racc[tid + 192];
        float4 r;
        r.x = (a.x + b.x + c2.x + d2.x) * Binv;
        r.y = (a.y + b.y + c2.y + d2.y) * Binv;
        r.z = (a.z + b.z + c2.z + d2.z) * Binv;
        r.w = (a.w + b.w + c2.w + d2.w) * Binv;
        ((float4*)g_eh)[e * 64 + tid] = r;
    }
}

__device__ __forceinline__ float eluf(float x) { return x > 0.f ? x : expm1f(x); }

// ---------------- conv1 node stage ----------------
__global__ __launch_bounds__(256) void node1_kernel(const int* __restrict__ hedgeIdx,
                                                    const float* __restrict__ b1) {
    int n = blockIdx.x;
    int tid = threadIdx.x;
    int beg = g_offN[n];
    int d = g_cntN[n];
    int end = beg + d;
    float Dinv = d > 0 ? 1.f / (float)d : 0.f;
    int g = tid >> 6, f4 = tid & 63, h = f4 >> 4;
    float4 acc = make_float4(0.f, 0.f, 0.f, 0.f);
    const float4* eh4 = (const float4*)g_eh;
    for (int j = beg + g; j < end; j += 4) {
        int i = g_csrN[j];
        int e = hedgeIdx[i];
        float a = g_alpha[i * 4 + h];
        float4 ev = eh4[e * 64 + f4];
        acc.x += a * ev.x; acc.y += a * ev.y; acc.z += a * ev.z; acc.w += a * ev.w;
    }
    __shared__ float4 racc[256];
    racc[tid] = acc;
    __syncthreads();
    if (tid < 64) {
        float4 a = racc[tid], b = racc[tid + 64], c2 = racc[tid + 128], d2 = racc[tid + 192];
        float4 bv = ((const float4*)b1)[tid];
        float4 r;
        r.x = eluf((a.x + b.x + c2.x + d2.x) * Dinv + bv.x);
        r.y = eluf((a.y + b.y + c2.y + d2.y) * Dinv + bv.y);
        r.z = eluf((a.z + b.z + c2.z + d2.z) * Dinv + bv.z);
        r.w = eluf((a.w + b.w + c2.w + d2.w) * Dinv + bv.w);
        ((float4*)g_h)[n * 64 + tid] = r;
    }
}

// ---------------- conv2 ----------------
__global__ __launch_bounds__(256) void edge2_kernel(const int* __restrict__ nodeIdx) {
    int e = blockIdx.x;
    int tid = threadIdx.x;
    int beg = g_offE[e];
    int k = g_cntE[e];
    int end = beg + k;
    float Binv = k > 0 ? 1.f / (float)k : 0.f;
    int g = tid >> 6, f = tid & 63;
    float acc = 0.f;
    for (int j = beg + g; j < end; j += 4) {
        int i = g_csrE[j];
        int n = nodeIdx[i];
        acc += g_xh2[n * 64 + f];
    }
    __shared__ float racc[256];
    racc[tid] = acc;
    __syncthreads();
    if (tid < 64)
        g_eh2[e * 64 + tid] = (racc[tid] + racc[tid + 64] + racc[tid + 128] + racc[tid + 192]) * Binv;
}

__global__ __launch_bounds__(256) void node2_kernel(const int* __restrict__ hedgeIdx,
                                                    const float* __restrict__ b2,
                                                    float* __restrict__ out) {
    int n = blockIdx.x;
    int tid = threadIdx.x;
    int beg = g_offN[n];
    int d = g_cntN[n];
    int end = beg + d;
    float Dinv = d > 0 ? 1.f / (float)d : 0.f;
    int g = tid >> 6, f = tid & 63;
    float acc = 0.f;
    for (int j = beg + g; j < end; j += 4) {
        int i = g_csrN[j];
        int e = hedgeIdx[i];
        acc += g_eh2[e * 64 + f];
    }
    __shared__ float racc[256];
    racc[tid] = acc;
    __syncthreads();
    if (tid < 64)
        out[n * 64 + tid] =
            (racc[tid] + racc[tid + 64] + racc[tid + 128] + racc[tid + 192]) * Dinv + b2[tid];
}

// ---------------- launch ----------------
extern "C" void kernel_launch(void* const* d_in, const int* in_sizes, int n_in,
                              void* d_out, int out_size) {
    const float* x    = (const float*)d_in[0];
    const int*   ei   = (const int*)d_in[1];
    const float* hat  = (const float*)d_in[2];
    const float* W1   = (const float*)d_in[3];
    const float* att1 = (const float*)d_in[4];
    const float* b1   = (const float*)d_in[5];
    const float* W2   = (const float*)d_in[6];
    const float* b2   = (const float*)d_in[7];
    float* out = (float*)d_out;

    int N   = in_sizes[0] / 128;
    int NNZ = in_sizes[1] / 2;
    int E   = in_sizes[2] / 128;
    const int* node  = ei;
    const int* hedge = ei + NNZ;

    float *p_xh, *p_h, *p_xh2;
    cudaGetSymbolAddress((void**)&p_xh, g_xh);
    cudaGetSymbolAddress((void**)&p_h, g_h);
    cudaGetSymbolAddress((void**)&p_xh2, g_xh2);

    // launch idx:            0            1        2       3 (profiled)  4
    zero_counts_kernel<<<128, 256>>>(N, E);
    count_kernel<<<480, 256>>>(node, hedge, NNZ);
    alloc_kernel<<<64, 256>>>(N, E);
    sgemm_kernel<128, 128, 16, 8, 8><<<dim3((N + 127) / 128, 2), 256>>>(x, W1, p_xh, N, 256, 128);
    scatter_kernel<<<480, 256>>>(node, hedge, NNZ);

    // attention logits via folded att (replaces E-GEMM + rowdots)
    attmat_kernel<<<1, 512>>>(W1, att1);
    axae_kernel<<<(N + E + 255) / 256, 256>>>(x, hat, N, E);

    // conv1: softmax + propagates + elu
    edge1_kernel<<<E, 256>>>(node);
    node1_kernel<<<N, 256>>>(hedge, b1);

    // conv2
    sgemm_kernel<128, 64, 16, 8, 4><<<dim3((N + 127) / 128, 1), 256>>>(p_h, W2, p_xh2, N, 64, 256);
    edge2_kernel<<<E, 256>>>(node);
    node2_kernel<<<N, 256>>>(hedge, b2, out);
}